// round 2
// baseline (speedup 1.0000x reference)
#include <cuda_runtime.h>
#include <cstdint>

typedef unsigned long long ull;

#define C_IN    64
#define H_IN    64
#define W_IN    64
#define NN      96
#define HOUT    60
#define WOUT    60
#define BATCH   16
#define DTOT    1600        // C_IN * 25
#define NITERS  5
#define FEPS    1e-20f

#define TY      4
#define TX      12
#define NTHREADS 192        // 48 positions * 4 threads
#define XS_H    8           // TY + 4
#define XS_W    16          // TX + 4
#define XS_ELEMS (C_IN * XS_H * XS_W)   // 8192 floats = 32 KB
#define WCHUNK  (C_IN * NN)             // 6144 floats = 24.5 KB
#define SMEM_BYTES ((XS_ELEMS + 2 * WCHUNK) * 4)  // 81920 B

// Device scratch (no allocations allowed in kernel_launch)
__device__ __align__(16) float g_Wr[25 * WCHUNK];          // W repacked [kk][c][n]
__device__ float g_csum[BATCH * H_IN * W_IN];              // sum over channels
__device__ float g_invs[BATCH * HOUT * WOUT];              // 1/(patch sum + eps)

// ---------------- packed f32x2 helpers (Blackwell) ----------------
__device__ __forceinline__ ull pack2(float lo, float hi) {
    ull r; asm("mov.b64 %0, {%1, %2};" : "=l"(r) : "f"(lo), "f"(hi)); return r;
}
__device__ __forceinline__ void unpack2(ull v, float& lo, float& hi) {
    asm("mov.b64 {%0, %1}, %2;" : "=f"(lo), "=f"(hi) : "l"(v));
}
__device__ __forceinline__ ull ffma2(ull a, ull b, ull c) {
    ull d; asm("fma.rn.f32x2 %0, %1, %2, %3;" : "=l"(d) : "l"(a), "l"(b), "l"(c)); return d;
}
__device__ __forceinline__ ull fmul2(ull a, ull b) {
    ull d; asm("mul.rn.f32x2 %0, %1, %2;" : "=l"(d) : "l"(a), "l"(b)); return d;
}

// ---------------- cp.async helpers ----------------
__device__ __forceinline__ void cp16(uint32_t dst_smem, const float* src) {
    asm volatile("cp.async.cg.shared.global [%0], [%1], 16;" :: "r"(dst_smem), "l"(src));
}
__device__ __forceinline__ void cp_commit() {
    asm volatile("cp.async.commit_group;");
}
template <int N>
__device__ __forceinline__ void cp_wait() {
    asm volatile("cp.async.wait_group %0;" :: "n"(N));
}
__device__ __forceinline__ void copy_chunk(float* dst, const float* src, int tid) {
    uint32_t d0 = (uint32_t)__cvta_generic_to_shared(dst);
    #pragma unroll
    for (int i = 0; i < (WCHUNK / 4) / NTHREADS; ++i) {   // 1536/192 = 8
        int j = tid + i * NTHREADS;
        cp16(d0 + j * 16, src + j * 4);
    }
}

// ---------------- precompute kernels ----------------
__global__ void repack_w_kernel(const float* __restrict__ w) {
    int idx = blockIdx.x * blockDim.x + threadIdx.x;
    if (idx >= DTOT * NN) return;
    int kk = idx / WCHUNK;
    int r  = idx % WCHUNK;
    int c  = r / NN;
    int n  = r % NN;
    g_Wr[idx] = w[(c * 25 + kk) * NN + n];
}

__global__ void csum_kernel(const float* __restrict__ x) {
    int idx = blockIdx.x * blockDim.x + threadIdx.x;
    if (idx >= BATCH * H_IN * W_IN) return;
    int b = idx >> 12;
    int p = idx & 4095;
    const float* xp = x + (size_t)b * C_IN * 4096 + p;
    float s = 0.f;
    #pragma unroll
    for (int c = 0; c < C_IN; ++c) s += xp[c * 4096];
    g_csum[idx] = s;
}

__global__ void invs_kernel() {
    int idx = blockIdx.x * blockDim.x + threadIdx.x;
    if (idx >= BATCH * HOUT * WOUT) return;
    int b = idx / (HOUT * WOUT);
    int r = idx % (HOUT * WOUT);
    int y = r / WOUT;
    int xp = r % WOUT;
    float s = 0.f;
    #pragma unroll
    for (int ki = 0; ki < 5; ++ki)
        #pragma unroll
        for (int kj = 0; kj < 5; ++kj)
            s += g_csum[b * 4096 + (y + ki) * 64 + (xp + kj)];
    g_invs[idx] = 1.0f / (s + FEPS);
}

// ---------------- main fused NNMF kernel ----------------
union F4U2 { float4 f4; ull u2[2]; };

extern __shared__ float smem_dyn[];

__global__ void __launch_bounds__(NTHREADS, 2)
nnmf_main(const float* __restrict__ x, float* __restrict__ out) {
    float* xs = smem_dyn;                 // [C_IN][XS_H][XS_W]
    float* ws = smem_dyn + XS_ELEMS;      // [2][C_IN][NN]

    const int b  = blockIdx.z;
    const int y0 = blockIdx.y * TY;
    const int x0 = blockIdx.x * TX;
    const int tid = threadIdx.x;
    const int q   = tid & 3;              // quad lane -> n slice
    const int gid = tid >> 2;             // position within tile
    const int py  = gid / TX;
    const int px  = gid % TX;
    const int n0  = q * 24;

    // Load x tile into smem (float4, coalesced; x0 is a multiple of 12 -> 16B aligned)
    {
        const int nf4 = XS_ELEMS / 4;     // 2048
        for (int i = tid; i < nf4; i += NTHREADS) {
            int c   = i >> 5;             // 32 float4 per channel
            int rr  = i & 31;
            int dy  = rr >> 2;
            int dxq = rr & 3;
            const float4 v = *(const float4*)(x + (((size_t)(b * C_IN + c) * H_IN + (y0 + dy)) * W_IN + x0) + dxq * 4);
            *(float4*)(xs + c * (XS_H * XS_W) + dy * XS_W + dxq * 4) = v;
        }
    }

    // Prefetch W chunk 0
    copy_chunk(ws, g_Wr, tid);
    cp_commit();

    const float inv_sp = g_invs[(b * HOUT + (y0 + py)) * WOUT + (x0 + px)];

    ull h2[12], t2[12];
    const ull hinit = pack2(1.0f / 96.0f, 1.0f / 96.0f);
    #pragma unroll
    for (int i = 0; i < 12; ++i) h2[i] = hinit;

    for (int it = 0; it < NITERS; ++it) {
        const ull zz = pack2(0.f, 0.f);
        #pragma unroll
        for (int i = 0; i < 12; ++i) t2[i] = zz;

        for (int kk = 0; kk < 25; ++kk) {
            const int kks = it * 25 + kk;
            float* wsbuf = ws + (kks & 1) * WCHUNK;
            if (kks < NITERS * 25 - 1) {
                copy_chunk(ws + ((kks + 1) & 1) * WCHUNK,
                           g_Wr + ((kk + 1) % 25) * WCHUNK, tid);
                cp_commit();
                cp_wait<1>();
            } else {
                cp_wait<0>();
            }
            __syncthreads();

            const int ki = kk / 5, kj = kk % 5;
            const float* xrow = xs + (py + ki) * XS_W + (px + kj);
            const float* wbase = wsbuf + n0;

            #pragma unroll 2
            for (int c = 0; c < C_IN; ++c) {
                // load this thread's 24 W values (6x float4, conflict-free broadcast)
                ull w2[12];
                #pragma unroll
                for (int i = 0; i < 6; ++i) {
                    F4U2 v; v.f4 = *(const float4*)(wbase + c * NN + i * 4);
                    w2[2 * i]     = v.u2[0];
                    w2[2 * i + 1] = v.u2[1];
                }
                // partial denom = dot(Wrow_slice, h_slice), packed, 2 accumulators
                ull a0 = fmul2(w2[0], h2[0]);
                ull a1 = fmul2(w2[1], h2[1]);
                #pragma unroll
                for (int i = 2; i < 12; i += 2) {
                    a0 = ffma2(w2[i],     h2[i],     a0);
                    a1 = ffma2(w2[i + 1], h2[i + 1], a1);
                }
                float dlo, dhi, elo, ehi;
                unpack2(a0, dlo, dhi);
                unpack2(a1, elo, ehi);
                float dd = (dlo + dhi) + (elo + ehi);
                // reduce across the quad -> full 96-dot
                dd += __shfl_xor_sync(0xffffffffu, dd, 1);
                dd += __shfl_xor_sync(0xffffffffu, dd, 2);
                // ratio = X_d / (denom + eps), X_d = u * inv_s
                const float u = xrow[c * (XS_H * XS_W)];
                const float rr = __fdividef(u * inv_sp, dd + FEPS);
                const ull r2 = pack2(rr, rr);
                // t += Wrow_slice * ratio
                #pragma unroll
                for (int i = 0; i < 12; ++i) t2[i] = ffma2(w2[i], r2, t2[i]);
            }
            __syncthreads();
        }

        // h = h * (1 + t); h /= (sum_n h + eps)
        #pragma unroll
        for (int i = 0; i < 12; ++i) h2[i] = ffma2(h2[i], t2[i], h2[i]);
        float s = 0.f;
        #pragma unroll
        for (int i = 0; i < 12; ++i) {
            float lo, hi; unpack2(h2[i], lo, hi);
            s += lo + hi;
        }
        s += __shfl_xor_sync(0xffffffffu, s, 1);
        s += __shfl_xor_sync(0xffffffffu, s, 2);
        const float rs = __fdividef(1.0f, s + FEPS);
        const ull rs2 = pack2(rs, rs);
        #pragma unroll
        for (int i = 0; i < 12; ++i) h2[i] = fmul2(h2[i], rs2);
    }

    // write output: out[b][n][y][x]
    const int yy = y0 + py, xx = x0 + px;
    #pragma unroll
    for (int i = 0; i < 12; ++i) {
        float lo, hi; unpack2(h2[i], lo, hi);
        const int n = n0 + 2 * i;
        out[((size_t)(b * NN + n)     * HOUT + yy) * WOUT + xx] = lo;
        out[((size_t)(b * NN + n + 1) * HOUT + yy) * WOUT + xx] = hi;
    }
}

// ---------------- launch ----------------
extern "C" void kernel_launch(void* const* d_in, const int* in_sizes, int n_in,
                              void* d_out, int out_size) {
    const float* x = (const float*)d_in[0];
    const float* w = (const float*)d_in[1];
    // defensive: identify by size if order differs
    if (n_in >= 2 && in_sizes[0] == DTOT * NN && in_sizes[1] == BATCH * C_IN * H_IN * W_IN) {
        const float* t = x; x = w; w = t;
    }
    float* out = (float*)d_out;

    repack_w_kernel<<<(DTOT * NN + 255) / 256, 256>>>(w);
    csum_kernel<<<(BATCH * H_IN * W_IN + 255) / 256, 256>>>(x);
    invs_kernel<<<(BATCH * HOUT * WOUT + 255) / 256, 256>>>();

    cudaFuncSetAttribute(nnmf_main, cudaFuncAttributeMaxDynamicSharedMemorySize, SMEM_BYTES);
    dim3 grid(WOUT / TX, HOUT / TY, BATCH);   // (5, 15, 16) = 1200 blocks
    nnmf_main<<<grid, NTHREADS, SMEM_BYTES>>>(x, out);
}

// round 3
// speedup vs baseline: 1.0381x; 1.0381x over previous
#include <cuda_runtime.h>
#include <cstdint>

typedef unsigned long long ull;

#define C_IN    64
#define H_IN    64
#define W_IN    64
#define NN      96
#define HOUT    60
#define WOUT    60
#define BATCH   16
#define DTOT    1600        // C_IN * 25
#define NITERS  5
#define FEPS    1e-20f

#define TY      4
#define TX      12
#define NTHREADS 192        // 48 positions * 4 threads
#define XS_H    8           // TY + 4
#define XS_W    16          // TX + 4
#define XS_ELEMS (C_IN * XS_H * XS_W)   // 8192 floats = 32 KB
#define CHALF   32                       // channels per W chunk
#define WCH     (CHALF * NN)             // 3072 floats = 12 KB
#define NCHUNK  50                       // chunks per iteration (25 kk * 2 halves)
#define SMEM_BYTES ((XS_ELEMS + 2 * WCH) * 4)   // 57344 B

// Device scratch (no allocations allowed in kernel_launch)
__device__ __align__(16) float g_Wr[NCHUNK * WCH];         // W repacked [kk][c][n]
__device__ float g_csum[BATCH * H_IN * W_IN];              // sum over channels
__device__ float g_invs[BATCH * HOUT * WOUT];              // 1/(patch sum + eps)

// ---------------- packed f32x2 helpers (Blackwell) ----------------
__device__ __forceinline__ ull pack2(float lo, float hi) {
    ull r; asm("mov.b64 %0, {%1, %2};" : "=l"(r) : "f"(lo), "f"(hi)); return r;
}
__device__ __forceinline__ void unpack2(ull v, float& lo, float& hi) {
    asm("mov.b64 {%0, %1}, %2;" : "=f"(lo), "=f"(hi) : "l"(v));
}
__device__ __forceinline__ ull ffma2(ull a, ull b, ull c) {
    ull d; asm("fma.rn.f32x2 %0, %1, %2, %3;" : "=l"(d) : "l"(a), "l"(b), "l"(c)); return d;
}
__device__ __forceinline__ ull fmul2(ull a, ull b) {
    ull d; asm("mul.rn.f32x2 %0, %1, %2;" : "=l"(d) : "l"(a), "l"(b)); return d;
}
__device__ __forceinline__ ull fadd2(ull a, ull b) {
    ull d; asm("add.rn.f32x2 %0, %1, %2;" : "=l"(d) : "l"(a), "l"(b)); return d;
}

// ---------------- cp.async helpers ----------------
__device__ __forceinline__ void cp16(uint32_t dst_smem, const float* src) {
    asm volatile("cp.async.cg.shared.global [%0], [%1], 16;" :: "r"(dst_smem), "l"(src));
}
__device__ __forceinline__ void cp_commit() {
    asm volatile("cp.async.commit_group;");
}
template <int N>
__device__ __forceinline__ void cp_wait() {
    asm volatile("cp.async.wait_group %0;" :: "n"(N));
}
__device__ __forceinline__ void copy_chunk(float* dst, const float* src, int tid) {
    uint32_t d0 = (uint32_t)__cvta_generic_to_shared(dst);
    #pragma unroll
    for (int i = 0; i < (WCH / 4) / NTHREADS; ++i) {   // 768/192 = 4
        int j = tid + i * NTHREADS;
        cp16(d0 + j * 16, src + j * 4);
    }
}

// ---------------- precompute kernels ----------------
__global__ void repack_w_kernel(const float* __restrict__ w) {
    // g_Wr layout: chunk j = kk*2 + half, within chunk [c_local][n]
    int idx = blockIdx.x * blockDim.x + threadIdx.x;
    if (idx >= DTOT * NN) return;
    int j  = idx / WCH;           // chunk
    int r  = idx % WCH;
    int cl = r / NN;              // local channel (0..31)
    int n  = r % NN;
    int kk = j >> 1;
    int c  = (j & 1) * CHALF + cl;
    g_Wr[idx] = w[(c * 25 + kk) * NN + n];
}

__global__ void csum_kernel(const float* __restrict__ x) {
    int idx = blockIdx.x * blockDim.x + threadIdx.x;
    if (idx >= BATCH * H_IN * W_IN) return;
    int b = idx >> 12;
    int p = idx & 4095;
    const float* xp = x + (size_t)b * C_IN * 4096 + p;
    float s = 0.f;
    #pragma unroll
    for (int c = 0; c < C_IN; ++c) s += xp[c * 4096];
    g_csum[idx] = s;
}

__global__ void invs_kernel() {
    int idx = blockIdx.x * blockDim.x + threadIdx.x;
    if (idx >= BATCH * HOUT * WOUT) return;
    int b = idx / (HOUT * WOUT);
    int r = idx % (HOUT * WOUT);
    int y = r / WOUT;
    int xp = r % WOUT;
    float s = 0.f;
    #pragma unroll
    for (int ki = 0; ki < 5; ++ki)
        #pragma unroll
        for (int kj = 0; kj < 5; ++kj)
            s += g_csum[b * 4096 + (y + ki) * 64 + (xp + kj)];
    g_invs[idx] = 1.0f / (s + FEPS);
}

// ---------------- main fused NNMF kernel ----------------
union F4U2 { float4 f4; ull u2[2]; };

extern __shared__ float smem_dyn[];

__global__ void __launch_bounds__(NTHREADS, 3)
nnmf_main(const float* __restrict__ x, float* __restrict__ out) {
    float* xs = smem_dyn;                 // [C_IN][XS_H][XS_W]
    float* ws = smem_dyn + XS_ELEMS;      // [2][CHALF][NN]

    const int b  = blockIdx.z;
    const int y0 = blockIdx.y * TY;
    const int x0 = blockIdx.x * TX;
    const int tid = threadIdx.x;
    const int q   = tid & 3;              // quad lane -> n slice
    const int gid = tid >> 2;             // position within tile
    const int py  = gid / TX;
    const int px  = gid % TX;
    const int n0  = q * 24;

    // Load x tile into smem (float4, coalesced; x0 is a multiple of 12 -> 16B aligned)
    {
        const int nf4 = XS_ELEMS / 4;     // 2048
        for (int i = tid; i < nf4; i += NTHREADS) {
            int c   = i >> 5;             // 32 float4 per channel
            int rr  = i & 31;
            int dy  = rr >> 2;
            int dxq = rr & 3;
            const float4 v = *(const float4*)(x + (((size_t)(b * C_IN + c) * H_IN + (y0 + dy)) * W_IN + x0) + dxq * 4);
            *(float4*)(xs + c * (XS_H * XS_W) + dy * XS_W + dxq * 4) = v;
        }
    }

    // Prefetch W chunk 0
    copy_chunk(ws, g_Wr, tid);
    cp_commit();

    const float inv_sp = g_invs[(b * HOUT + (y0 + py)) * WOUT + (x0 + px)];

    ull h2[12], t2[12];
    const ull hinit = pack2(1.0f / 96.0f, 1.0f / 96.0f);
    #pragma unroll
    for (int i = 0; i < 12; ++i) h2[i] = hinit;

    for (int it = 0; it < NITERS; ++it) {
        const ull zz = pack2(0.f, 0.f);
        #pragma unroll
        for (int i = 0; i < 12; ++i) t2[i] = zz;

        for (int ch = 0; ch < NCHUNK; ++ch) {
            const int cs = it * NCHUNK + ch;
            float* wsbuf = ws + (cs & 1) * WCH;
            if (cs < NITERS * NCHUNK - 1) {
                copy_chunk(ws + ((cs + 1) & 1) * WCH,
                           g_Wr + ((ch + 1) % NCHUNK) * WCH, tid);
                cp_commit();
                cp_wait<1>();
            } else {
                cp_wait<0>();
            }
            __syncthreads();

            const int kk = ch >> 1;
            const int ki = kk / 5, kj = kk % 5;
            // absolute channel base for this half-chunk
            const float* xrow = xs + (ch & 1) * CHALF * (XS_H * XS_W)
                                   + (py + ki) * XS_W + (px + kj);
            const float* wbase = wsbuf + n0;

            #pragma unroll 2
            for (int cc = 0; cc < CHALF; ++cc) {
                // load this thread's 24 W values (6x float4, conflict-free broadcast)
                ull w2[12];
                #pragma unroll
                for (int i = 0; i < 6; ++i) {
                    F4U2 v; v.f4 = *(const float4*)(wbase + cc * NN + i * 4);
                    w2[2 * i]     = v.u2[0];
                    w2[2 * i + 1] = v.u2[1];
                }
                // partial denom = dot(Wrow_slice, h_slice), packed, 2 accumulators
                ull a0 = fmul2(w2[0], h2[0]);
                ull a1 = fmul2(w2[1], h2[1]);
                #pragma unroll
                for (int i = 2; i < 12; i += 2) {
                    a0 = ffma2(w2[i],     h2[i],     a0);
                    a1 = ffma2(w2[i + 1], h2[i + 1], a1);
                }
                a0 = fadd2(a0, a1);
                float dlo, dhi;
                unpack2(a0, dlo, dhi);
                float dd = dlo + dhi;
                // reduce across the quad -> full 96-dot
                dd += __shfl_xor_sync(0xffffffffu, dd, 1);
                dd += __shfl_xor_sync(0xffffffffu, dd, 2);
                // ratio = X_d / (denom + eps), X_d = u * inv_s
                const float u = xrow[cc * (XS_H * XS_W)];
                const float rr = __fdividef(u * inv_sp, dd + FEPS);
                const ull r2 = pack2(rr, rr);
                // t += Wrow_slice * ratio
                #pragma unroll
                for (int i = 0; i < 12; ++i) t2[i] = ffma2(w2[i], r2, t2[i]);
            }
            __syncthreads();
        }

        // h = h * (1 + t); h /= (sum_n h + eps)
        #pragma unroll
        for (int i = 0; i < 12; ++i) h2[i] = ffma2(h2[i], t2[i], h2[i]);
        ull s2 = fadd2(h2[0], h2[1]);
        #pragma unroll
        for (int i = 2; i < 12; ++i) s2 = fadd2(s2, h2[i]);
        float slo, shi;
        unpack2(s2, slo, shi);
        float s = slo + shi;
        s += __shfl_xor_sync(0xffffffffu, s, 1);
        s += __shfl_xor_sync(0xffffffffu, s, 2);
        const float rs = __fdividef(1.0f, s + FEPS);
        const ull rs2 = pack2(rs, rs);
        #pragma unroll
        for (int i = 0; i < 12; ++i) h2[i] = fmul2(h2[i], rs2);
    }

    // write output: out[b][n][y][x]
    const int yy = y0 + py, xx = x0 + px;
    #pragma unroll
    for (int i = 0; i < 12; ++i) {
        float lo, hi; unpack2(h2[i], lo, hi);
        const int n = n0 + 2 * i;
        out[((size_t)(b * NN + n)     * HOUT + yy) * WOUT + xx] = lo;
        out[((size_t)(b * NN + n + 1) * HOUT + yy) * WOUT + xx] = hi;
    }
}

// ---------------- launch ----------------
extern "C" void kernel_launch(void* const* d_in, const int* in_sizes, int n_in,
                              void* d_out, int out_size) {
    const float* x = (const float*)d_in[0];
    const float* w = (const float*)d_in[1];
    // defensive: identify by size if order differs
    if (n_in >= 2 && in_sizes[0] == DTOT * NN && in_sizes[1] == BATCH * C_IN * H_IN * W_IN) {
        const float* t = x; x = w; w = t;
    }
    float* out = (float*)d_out;

    repack_w_kernel<<<(DTOT * NN + 255) / 256, 256>>>(w);
    csum_kernel<<<(BATCH * H_IN * W_IN + 255) / 256, 256>>>(x);
    invs_kernel<<<(BATCH * HOUT * WOUT + 255) / 256, 256>>>();

    cudaFuncSetAttribute(nnmf_main, cudaFuncAttributeMaxDynamicSharedMemorySize, SMEM_BYTES);
    dim3 grid(WOUT / TX, HOUT / TY, BATCH);   // (5, 15, 16) = 1200 blocks
    nnmf_main<<<grid, NTHREADS, SMEM_BYTES>>>(x, out);
}

// round 4
// speedup vs baseline: 1.0387x; 1.0006x over previous
#include <cuda_runtime.h>
#include <cstdint>

typedef unsigned long long ull;

#define C_IN    64
#define H_IN    64
#define W_IN    64
#define NN      96
#define HOUT    60
#define WOUT    60
#define BATCH   16
#define DTOT    1600        // C_IN * 25
#define NITERS  5
#define FEPS    1e-20f

#define TY      4
#define TX      12
#define NTHREADS 192        // 48 positions * 4 threads
#define XS_H    8           // TY + 4
#define XS_W    16          // TX + 4
#define XS_ELEMS (C_IN * XS_H * XS_W)   // 8192 floats = 32 KB
#define CHALF   32                       // channels per W chunk
#define WCH     (CHALF * NN)             // 3072 floats = 12 KB
#define NCHUNK  50                       // chunks per iteration (25 kk * 2 halves)
#define SMEM_BYTES ((XS_ELEMS + 2 * WCH) * 4)   // 57344 B

// Device scratch (no allocations allowed in kernel_launch)
__device__ __align__(16) float g_Wr[NCHUNK * WCH];         // W repacked [kk][c][n]
__device__ float g_csum[BATCH * H_IN * W_IN];              // sum over channels
__device__ float g_invs[BATCH * HOUT * WOUT];              // 1/(patch sum + eps)

// ---------------- packed f32x2 helpers (Blackwell) ----------------
__device__ __forceinline__ ull pack2(float lo, float hi) {
    ull r; asm("mov.b64 %0, {%1, %2};" : "=l"(r) : "f"(lo), "f"(hi)); return r;
}
__device__ __forceinline__ void unpack2(ull v, float& lo, float& hi) {
    asm("mov.b64 {%0, %1}, %2;" : "=f"(lo), "=f"(hi) : "l"(v));
}
__device__ __forceinline__ ull ffma2(ull a, ull b, ull c) {
    ull d; asm("fma.rn.f32x2 %0, %1, %2, %3;" : "=l"(d) : "l"(a), "l"(b), "l"(c)); return d;
}
__device__ __forceinline__ ull fmul2(ull a, ull b) {
    ull d; asm("mul.rn.f32x2 %0, %1, %2;" : "=l"(d) : "l"(a), "l"(b)); return d;
}
__device__ __forceinline__ ull fadd2(ull a, ull b) {
    ull d; asm("add.rn.f32x2 %0, %1, %2;" : "=l"(d) : "l"(a), "l"(b)); return d;
}

// ---------------- cp.async helpers ----------------
__device__ __forceinline__ void cp16(uint32_t dst_smem, const float* src) {
    asm volatile("cp.async.cg.shared.global [%0], [%1], 16;" :: "r"(dst_smem), "l"(src));
}
__device__ __forceinline__ void cp_commit() {
    asm volatile("cp.async.commit_group;");
}
template <int N>
__device__ __forceinline__ void cp_wait() {
    asm volatile("cp.async.wait_group %0;" :: "n"(N));
}
__device__ __forceinline__ void copy_chunk(float* dst, const float* src, int tid) {
    uint32_t d0 = (uint32_t)__cvta_generic_to_shared(dst);
    #pragma unroll
    for (int i = 0; i < (WCH / 4) / NTHREADS; ++i) {   // 768/192 = 4
        int j = tid + i * NTHREADS;
        cp16(d0 + j * 16, src + j * 4);
    }
}

// ---------------- precompute kernels ----------------
__global__ void repack_w_kernel(const float* __restrict__ w) {
    // g_Wr layout: chunk j = kk*2 + half, within chunk [c_local][n]
    int idx = blockIdx.x * blockDim.x + threadIdx.x;
    if (idx >= DTOT * NN) return;
    int j  = idx / WCH;           // chunk
    int r  = idx % WCH;
    int cl = r / NN;              // local channel (0..31)
    int n  = r % NN;
    int kk = j >> 1;
    int c  = (j & 1) * CHALF + cl;
    g_Wr[idx] = w[(c * 25 + kk) * NN + n];
}

__global__ void csum_kernel(const float* __restrict__ x) {
    int idx = blockIdx.x * blockDim.x + threadIdx.x;
    if (idx >= BATCH * H_IN * W_IN) return;
    int b = idx >> 12;
    int p = idx & 4095;
    const float* xp = x + (size_t)b * C_IN * 4096 + p;
    float s = 0.f;
    #pragma unroll
    for (int c = 0; c < C_IN; ++c) s += xp[c * 4096];
    g_csum[idx] = s;
}

__global__ void invs_kernel() {
    int idx = blockIdx.x * blockDim.x + threadIdx.x;
    if (idx >= BATCH * HOUT * WOUT) return;
    int b = idx / (HOUT * WOUT);
    int r = idx % (HOUT * WOUT);
    int y = r / WOUT;
    int xp = r % WOUT;
    float s = 0.f;
    #pragma unroll
    for (int ki = 0; ki < 5; ++ki)
        #pragma unroll
        for (int kj = 0; kj < 5; ++kj)
            s += g_csum[b * 4096 + (y + ki) * 64 + (xp + kj)];
    g_invs[idx] = 1.0f / (s + FEPS);
}

// ---------------- main fused NNMF kernel ----------------
union F4U2 { float4 f4; ull u2[2]; };

extern __shared__ float smem_dyn[];

__global__ void __launch_bounds__(NTHREADS, 3)
nnmf_main(const float* __restrict__ x, float* __restrict__ out) {
    float* xs = smem_dyn;                 // [C_IN][XS_H][XS_W]
    float* ws = smem_dyn + XS_ELEMS;      // [2][CHALF][NN]

    const int b  = blockIdx.z;
    const int y0 = blockIdx.y * TY;
    const int x0 = blockIdx.x * TX;
    const int tid = threadIdx.x;
    const int q   = tid & 3;              // quad lane -> n slice
    const int gid = tid >> 2;             // position within tile
    const int py  = gid / TX;
    const int px  = gid % TX;
    const int n0  = q * 24;

    // Load x tile into smem (float4, coalesced; x0 is a multiple of 12 -> 16B aligned)
    {
        const int nf4 = XS_ELEMS / 4;     // 2048
        for (int i = tid; i < nf4; i += NTHREADS) {
            int c   = i >> 5;             // 32 float4 per channel
            int rr  = i & 31;
            int dy  = rr >> 2;
            int dxq = rr & 3;
            const float4 v = *(const float4*)(x + (((size_t)(b * C_IN + c) * H_IN + (y0 + dy)) * W_IN + x0) + dxq * 4);
            *(float4*)(xs + c * (XS_H * XS_W) + dy * XS_W + dxq * 4) = v;
        }
    }

    // Prefetch W chunk 0
    copy_chunk(ws, g_Wr, tid);
    cp_commit();

    const float inv_sp = g_invs[(b * HOUT + (y0 + py)) * WOUT + (x0 + px)];

    ull h2[12], t2[12];
    const ull hinit = pack2(1.0f / 96.0f, 1.0f / 96.0f);
    #pragma unroll
    for (int i = 0; i < 12; ++i) h2[i] = hinit;

    for (int it = 0; it < NITERS; ++it) {
        const ull zz = pack2(0.f, 0.f);
        #pragma unroll
        for (int i = 0; i < 12; ++i) t2[i] = zz;

        for (int ch = 0; ch < NCHUNK; ++ch) {
            const int cs = it * NCHUNK + ch;
            float* wsbuf = ws + (cs & 1) * WCH;
            if (cs < NITERS * NCHUNK - 1) {
                copy_chunk(ws + ((cs + 1) & 1) * WCH,
                           g_Wr + ((ch + 1) % NCHUNK) * WCH, tid);
                cp_commit();
                cp_wait<1>();
            } else {
                cp_wait<0>();
            }
            __syncthreads();

            const int kk = ch >> 1;
            const int ki = kk / 5, kj = kk % 5;
            // absolute channel base for this half-chunk
            const float* xrow = xs + (ch & 1) * CHALF * (XS_H * XS_W)
                                   + (py + ki) * XS_W + (px + kj);
            const float* wbase = wsbuf + n0;

            #pragma unroll 2
            for (int cc = 0; cc < CHALF; ++cc) {
                // load this thread's 24 W values (6x float4, conflict-free broadcast)
                ull w2[12];
                #pragma unroll
                for (int i = 0; i < 6; ++i) {
                    F4U2 v; v.f4 = *(const float4*)(wbase + cc * NN + i * 4);
                    w2[2 * i]     = v.u2[0];
                    w2[2 * i + 1] = v.u2[1];
                }
                // partial denom = dot(Wrow_slice, h_slice), packed, 2 accumulators
                ull a0 = fmul2(w2[0], h2[0]);
                ull a1 = fmul2(w2[1], h2[1]);
                #pragma unroll
                for (int i = 2; i < 12; i += 2) {
                    a0 = ffma2(w2[i],     h2[i],     a0);
                    a1 = ffma2(w2[i + 1], h2[i + 1], a1);
                }
                a0 = fadd2(a0, a1);
                float dlo, dhi;
                unpack2(a0, dlo, dhi);
                float dd = dlo + dhi;
                // reduce across the quad -> full 96-dot
                dd += __shfl_xor_sync(0xffffffffu, dd, 1);
                dd += __shfl_xor_sync(0xffffffffu, dd, 2);
                // ratio = X_d / (denom + eps), X_d = u * inv_s
                const float u = xrow[cc * (XS_H * XS_W)];
                const float rr = __fdividef(u * inv_sp, dd + FEPS);
                const ull r2 = pack2(rr, rr);
                // t += Wrow_slice * ratio
                #pragma unroll
                for (int i = 0; i < 12; ++i) t2[i] = ffma2(w2[i], r2, t2[i]);
            }
            __syncthreads();
        }

        // h = h * (1 + t); h /= (sum_n h + eps)
        #pragma unroll
        for (int i = 0; i < 12; ++i) h2[i] = ffma2(h2[i], t2[i], h2[i]);
        ull s2 = fadd2(h2[0], h2[1]);
        #pragma unroll
        for (int i = 2; i < 12; ++i) s2 = fadd2(s2, h2[i]);
        float slo, shi;
        unpack2(s2, slo, shi);
        float s = slo + shi;
        s += __shfl_xor_sync(0xffffffffu, s, 1);
        s += __shfl_xor_sync(0xffffffffu, s, 2);
        const float rs = __fdividef(1.0f, s + FEPS);
        const ull rs2 = pack2(rs, rs);
        #pragma unroll
        for (int i = 0; i < 12; ++i) h2[i] = fmul2(h2[i], rs2);
    }

    // write output: out[b][n][y][x]
    const int yy = y0 + py, xx = x0 + px;
    #pragma unroll
    for (int i = 0; i < 12; ++i) {
        float lo, hi; unpack2(h2[i], lo, hi);
        const int n = n0 + 2 * i;
        out[((size_t)(b * NN + n)     * HOUT + yy) * WOUT + xx] = lo;
        out[((size_t)(b * NN + n + 1) * HOUT + yy) * WOUT + xx] = hi;
    }
}

// ---------------- launch ----------------
extern "C" void kernel_launch(void* const* d_in, const int* in_sizes, int n_in,
                              void* d_out, int out_size) {
    const float* x = (const float*)d_in[0];
    const float* w = (const float*)d_in[1];
    // defensive: identify by size if order differs
    if (n_in >= 2 && in_sizes[0] == DTOT * NN && in_sizes[1] == BATCH * C_IN * H_IN * W_IN) {
        const float* t = x; x = w; w = t;
    }
    float* out = (float*)d_out;

    repack_w_kernel<<<(DTOT * NN + 255) / 256, 256>>>(w);
    csum_kernel<<<(BATCH * H_IN * W_IN + 255) / 256, 256>>>(x);
    invs_kernel<<<(BATCH * HOUT * WOUT + 255) / 256, 256>>>();

    cudaFuncSetAttribute(nnmf_main, cudaFuncAttributeMaxDynamicSharedMemorySize, SMEM_BYTES);
    dim3 grid(WOUT / TX, HOUT / TY, BATCH);   // (5, 15, 16) = 1200 blocks
    nnmf_main<<<grid, NTHREADS, SMEM_BYTES>>>(x, out);
}

// round 6
// speedup vs baseline: 1.2226x; 1.1770x over previous
#include <cuda_runtime.h>
#include <cstdint>

typedef unsigned long long ull;

#define C_IN    64
#define H_IN    64
#define W_IN    64
#define NN      96
#define HOUT    60
#define WOUT    60
#define BATCH   16
#define DTOT    1600
#define NITERS  5
#define FEPS    1e-20f

#define TY      4
#define TXP     6            // position-pairs per row
#define TX      12           // positions per row
#define NTHREADS 96          // 24 pairs * 4 quad-threads
#define XS_H    8            // TY + 4
#define XS_W    16           // TX + 4
#define XS_CH   (XS_H * XS_W)            // 128
#define XS_ELEMS (C_IN * XS_CH)          // 8192 floats = 32 KB
#define CHALF   32
#define WCH     (CHALF * NN)             // 3072 floats = 12 KB
#define NCHUNK  50
#define SMEM_BYTES ((XS_ELEMS + 2 * WCH) * 4)   // 57344 B

__device__ __align__(16) float g_Wr[NCHUNK * WCH];
__device__ float g_csum[BATCH * H_IN * W_IN];
__device__ float g_invs[BATCH * HOUT * WOUT];

// ---------------- packed f32x2 helpers ----------------
__device__ __forceinline__ ull pack2(float lo, float hi) {
    ull r; asm("mov.b64 %0, {%1, %2};" : "=l"(r) : "f"(lo), "f"(hi)); return r;
}
__device__ __forceinline__ void unpack2(ull v, float& lo, float& hi) {
    asm("mov.b64 {%0, %1}, %2;" : "=f"(lo), "=f"(hi) : "l"(v));
}
__device__ __forceinline__ ull ffma2(ull a, ull b, ull c) {
    ull d; asm("fma.rn.f32x2 %0, %1, %2, %3;" : "=l"(d) : "l"(a), "l"(b), "l"(c)); return d;
}
__device__ __forceinline__ ull fmul2(ull a, ull b) {
    ull d; asm("mul.rn.f32x2 %0, %1, %2;" : "=l"(d) : "l"(a), "l"(b)); return d;
}
__device__ __forceinline__ ull fadd2(ull a, ull b) {
    ull d; asm("add.rn.f32x2 %0, %1, %2;" : "=l"(d) : "l"(a), "l"(b)); return d;
}

// ---------------- cp.async helpers ----------------
__device__ __forceinline__ void cp16(uint32_t dst_smem, const float* src) {
    asm volatile("cp.async.cg.shared.global [%0], [%1], 16;" :: "r"(dst_smem), "l"(src));
}
__device__ __forceinline__ void cp_commit() { asm volatile("cp.async.commit_group;"); }
template <int N>
__device__ __forceinline__ void cp_wait() {
    asm volatile("cp.async.wait_group %0;" :: "n"(N));
}
__device__ __forceinline__ void copy_chunk(float* dst, const float* src, int tid) {
    uint32_t d0 = (uint32_t)__cvta_generic_to_shared(dst);
    #pragma unroll
    for (int i = 0; i < (WCH / 4) / NTHREADS; ++i) {   // 768/96 = 8
        int j = tid + i * NTHREADS;
        cp16(d0 + j * 16, src + j * 4);
    }
}

// ---------------- precompute kernels ----------------
__global__ void repack_w_kernel(const float* __restrict__ w) {
    int idx = blockIdx.x * blockDim.x + threadIdx.x;
    if (idx >= DTOT * NN) return;
    int j  = idx / WCH;
    int r  = idx % WCH;
    int cl = r / NN;
    int n  = r % NN;
    int kk = j >> 1;
    int c  = (j & 1) * CHALF + cl;
    g_Wr[idx] = w[(c * 25 + kk) * NN + n];
}

__global__ void csum_kernel(const float* __restrict__ x) {
    int idx = blockIdx.x * blockDim.x + threadIdx.x;
    if (idx >= BATCH * H_IN * W_IN) return;
    int b = idx >> 12;
    int p = idx & 4095;
    const float* xp = x + (size_t)b * C_IN * 4096 + p;
    float s = 0.f;
    #pragma unroll
    for (int c = 0; c < C_IN; ++c) s += xp[c * 4096];
    g_csum[idx] = s;
}

__global__ void invs_kernel() {
    int idx = blockIdx.x * blockDim.x + threadIdx.x;
    if (idx >= BATCH * HOUT * WOUT) return;
    int b = idx / (HOUT * WOUT);
    int r = idx % (HOUT * WOUT);
    int y = r / WOUT;
    int xp = r % WOUT;
    float s = 0.f;
    #pragma unroll
    for (int ki = 0; ki < 5; ++ki)
        #pragma unroll
        for (int kj = 0; kj < 5; ++kj)
            s += g_csum[b * 4096 + (y + ki) * 64 + (xp + kj)];
    g_invs[idx] = 1.0f / (s + FEPS);
}

// ---------------- main fused NNMF kernel ----------------
union F4U2 { float4 f4; ull u2[2]; };

extern __shared__ float smem_dyn[];

__global__ void __launch_bounds__(NTHREADS, 4)
nnmf_main(const float* __restrict__ x, float* __restrict__ out) {
    float* xs = smem_dyn;                 // [C_IN][XS_H][XS_W]
    float* ws = smem_dyn + XS_ELEMS;      // [2][CHALF][NN]

    const int b  = blockIdx.z;
    const int y0 = blockIdx.y * TY;
    const int x0 = blockIdx.x * TX;
    const int tid = threadIdx.x;
    const int q   = tid & 3;              // quad lane -> n slice
    const int gid = tid >> 2;             // pair id within tile (0..23)
    const int py  = gid / TXP;
    const int px  = (gid % TXP) * 2;      // even position of the pair
    const int n0  = q * 24;

    // Load x tile into smem (float4, coalesced)
    {
        const int nf4 = XS_ELEMS / 4;     // 2048
        for (int i = tid; i < nf4; i += NTHREADS) {
            int c   = i >> 5;
            int rr  = i & 31;
            int dy  = rr >> 2;
            int dxq = rr & 3;
            const float4 v = *(const float4*)(x + (((size_t)(b * C_IN + c) * H_IN + (y0 + dy)) * W_IN + x0) + dxq * 4);
            *(float4*)(xs + c * XS_CH + dy * XS_W + dxq * 4) = v;
        }
    }

    // Prefetch W chunk 0
    copy_chunk(ws, g_Wr, tid);
    cp_commit();

    const int yy = y0 + py;
    const float inv_a = g_invs[(b * HOUT + yy) * WOUT + (x0 + px)];
    const float inv_b = g_invs[(b * HOUT + yy) * WOUT + (x0 + px + 1)];

    ull ha[12], hb[12], ta[12], tb[12];
    const ull hinit = pack2(1.0f / 96.0f, 1.0f / 96.0f);
    #pragma unroll
    for (int i = 0; i < 12; ++i) { ha[i] = hinit; hb[i] = hinit; }

    for (int it = 0; it < NITERS; ++it) {
        const ull zz = pack2(0.f, 0.f);
        #pragma unroll
        for (int i = 0; i < 12; ++i) { ta[i] = zz; tb[i] = zz; }

        for (int ch = 0; ch < NCHUNK; ++ch) {
            const int cs = it * NCHUNK + ch;
            float* wsbuf = ws + (cs & 1) * WCH;
            if (cs < NITERS * NCHUNK - 1) {
                copy_chunk(ws + ((cs + 1) & 1) * WCH,
                           g_Wr + ((ch + 1) % NCHUNK) * WCH, tid);
                cp_commit();
                cp_wait<1>();
            } else {
                cp_wait<0>();
            }
            __syncthreads();

            const int kk = ch >> 1;
            const int ki = kk / 5, kj = kk % 5;
            const float* xrow = xs + (ch & 1) * CHALF * XS_CH
                                   + (py + ki) * XS_W + (px + kj);
            const float* wbase = wsbuf + n0;

            for (int cc = 0; cc < CHALF; ++cc) {
                // 24 W values (6x float4 LDS.128, broadcast across pairs)
                ull w2[12];
                #pragma unroll
                for (int i = 0; i < 6; ++i) {
                    F4U2 v; v.f4 = *(const float4*)(wbase + cc * NN + i * 4);
                    w2[2 * i]     = v.u2[0];
                    w2[2 * i + 1] = v.u2[1];
                }
                // x for both positions of the pair (early, overlap latency)
                const float u_a = xrow[cc * XS_CH];
                const float u_b = xrow[cc * XS_CH + 1];

                // denom partials for both positions
                ull a0 = fmul2(w2[0], ha[0]);
                ull a1 = fmul2(w2[1], ha[1]);
                ull b0 = fmul2(w2[0], hb[0]);
                ull b1 = fmul2(w2[1], hb[1]);
                #pragma unroll
                for (int i = 2; i < 12; i += 2) {
                    a0 = ffma2(w2[i],     ha[i],     a0);
                    a1 = ffma2(w2[i + 1], ha[i + 1], a1);
                    b0 = ffma2(w2[i],     hb[i],     b0);
                    b1 = ffma2(w2[i + 1], hb[i + 1], b1);
                }
                a0 = fadd2(a0, a1);
                b0 = fadd2(b0, b1);
                float alo, ahi, blo, bhi;
                unpack2(a0, alo, ahi);
                unpack2(b0, blo, bhi);
                float da = alo + ahi;
                float db = blo + bhi;
                da += __shfl_xor_sync(0xffffffffu, da, 1);
                db += __shfl_xor_sync(0xffffffffu, db, 1);
                da += __shfl_xor_sync(0xffffffffu, da, 2);
                db += __shfl_xor_sync(0xffffffffu, db, 2);

                const float ra = __fdividef(u_a * inv_a, da + FEPS);
                const float rb = __fdividef(u_b * inv_b, db + FEPS);
                const ull r2a = pack2(ra, ra);
                const ull r2b = pack2(rb, rb);
                #pragma unroll
                for (int i = 0; i < 12; ++i) {
                    ta[i] = ffma2(w2[i], r2a, ta[i]);
                    tb[i] = ffma2(w2[i], r2b, tb[i]);
                }
            }
            __syncthreads();
        }

        // h = h*(1+t); h /= (sum + eps)   (both positions)
        #pragma unroll
        for (int i = 0; i < 12; ++i) {
            ha[i] = ffma2(ha[i], ta[i], ha[i]);
            hb[i] = ffma2(hb[i], tb[i], hb[i]);
        }
        ull sa = fadd2(ha[0], ha[1]);
        ull sb = fadd2(hb[0], hb[1]);
        #pragma unroll
        for (int i = 2; i < 12; ++i) { sa = fadd2(sa, ha[i]); sb = fadd2(sb, hb[i]); }
        float slo, shi, tlo, thi;
        unpack2(sa, slo, shi);
        unpack2(sb, tlo, thi);
        float ssa = slo + shi;
        float ssb = tlo + thi;
        ssa += __shfl_xor_sync(0xffffffffu, ssa, 1);
        ssb += __shfl_xor_sync(0xffffffffu, ssb, 1);
        ssa += __shfl_xor_sync(0xffffffffu, ssa, 2);
        ssb += __shfl_xor_sync(0xffffffffu, ssb, 2);
        const float rsa = __fdividef(1.0f, ssa + FEPS);
        const float rsb = __fdividef(1.0f, ssb + FEPS);
        const ull rsa2 = pack2(rsa, rsa);
        const ull rsb2 = pack2(rsb, rsb);
        #pragma unroll
        for (int i = 0; i < 12; ++i) {
            ha[i] = fmul2(ha[i], rsa2);
            hb[i] = fmul2(hb[i], rsb2);
        }
    }

    // write output: out[b][n][y][x], position pair -> float2 store
    const int xx = x0 + px;
    #pragma unroll
    for (int i = 0; i < 12; ++i) {
        float alo, ahi, blo, bhi;
        unpack2(ha[i], alo, ahi);
        unpack2(hb[i], blo, bhi);
        const int n = n0 + 2 * i;
        *(float2*)(out + ((size_t)(b * NN + n)     * HOUT + yy) * WOUT + xx) = make_float2(alo, blo);
        *(float2*)(out + ((size_t)(b * NN + n + 1) * HOUT + yy) * WOUT + xx) = make_float2(ahi, bhi);
    }
}

// ---------------- launch ----------------
extern "C" void kernel_launch(void* const* d_in, const int* in_sizes, int n_in,
                              void* d_out, int out_size) {
    const float* x = (const float*)d_in[0];
    const float* w = (const float*)d_in[1];
    if (n_in >= 2 && in_sizes[0] == DTOT * NN && in_sizes[1] == BATCH * C_IN * H_IN * W_IN) {
        const float* t = x; x = w; w = t;
    }
    float* out = (float*)d_out;

    repack_w_kernel<<<(DTOT * NN + 255) / 256, 256>>>(w);
    csum_kernel<<<(BATCH * H_IN * W_IN + 255) / 256, 256>>>(x);
    invs_kernel<<<(BATCH * HOUT * WOUT + 255) / 256, 256>>>();

    cudaFuncSetAttribute(nnmf_main, cudaFuncAttributeMaxDynamicSharedMemorySize, SMEM_BYTES);
    dim3 grid(WOUT / TX, HOUT / TY, BATCH);   // (5, 15, 16) = 1200 blocks
    nnmf_main<<<grid, NTHREADS, SMEM_BYTES>>>(x, out);
}

// round 8
// speedup vs baseline: 1.2958x; 1.0599x over previous
#include <cuda_runtime.h>
#include <cstdint>

typedef unsigned long long ull;

#define C_IN    64
#define H_IN    64
#define W_IN    64
#define NN      96
#define HOUT    60
#define WOUT    60
#define BATCH   16
#define DTOT    1600
#define NITERS  5
#define FEPS    1e-20f

#define TY      4
#define TXP     6
#define TX      12
#define NTHREADS 96
#define XS_H    8
#define XS_W    16
#define XS_CH   (XS_H * XS_W)            // 128
#define XS_ELEMS (C_IN * XS_CH)          // 8192 floats = 32 KB
#define CHALF   32
#define WCH     (CHALF * NN)             // 3072 floats = 12 KB
#define NCHUNK  50
#define SMEM_BYTES ((XS_ELEMS + 2 * WCH) * 4)   // 57344 B

__device__ __align__(16) float g_Wr[NCHUNK * WCH];
__device__ float g_csum[BATCH * H_IN * W_IN];
__device__ float g_invs[BATCH * HOUT * WOUT];

// ---------------- packed f32x2 helpers ----------------
__device__ __forceinline__ ull pack2(float lo, float hi) {
    ull r; asm("mov.b64 %0, {%1, %2};" : "=l"(r) : "f"(lo), "f"(hi)); return r;
}
__device__ __forceinline__ void unpack2(ull v, float& lo, float& hi) {
    asm("mov.b64 {%0, %1}, %2;" : "=f"(lo), "=f"(hi) : "l"(v));
}
__device__ __forceinline__ ull ffma2(ull a, ull b, ull c) {
    ull d; asm("fma.rn.f32x2 %0, %1, %2, %3;" : "=l"(d) : "l"(a), "l"(b), "l"(c)); return d;
}
__device__ __forceinline__ ull fmul2(ull a, ull b) {
    ull d; asm("mul.rn.f32x2 %0, %1, %2;" : "=l"(d) : "l"(a), "l"(b)); return d;
}
__device__ __forceinline__ ull fadd2(ull a, ull b) {
    ull d; asm("add.rn.f32x2 %0, %1, %2;" : "=l"(d) : "l"(a), "l"(b)); return d;
}
__device__ __forceinline__ float frcp(float x) {
    float r; asm("rcp.approx.ftz.f32 %0, %1;" : "=f"(r) : "f"(x)); return r;
}

// ---------------- cp.async helpers ----------------
__device__ __forceinline__ void cp16(uint32_t dst_smem, const float* src) {
    asm volatile("cp.async.cg.shared.global [%0], [%1], 16;" :: "r"(dst_smem), "l"(src));
}
__device__ __forceinline__ void cp_commit() { asm volatile("cp.async.commit_group;"); }
template <int N>
__device__ __forceinline__ void cp_wait() {
    asm volatile("cp.async.wait_group %0;" :: "n"(N));
}
__device__ __forceinline__ void copy_chunk(float* dst, const float* src, int tid) {
    uint32_t d0 = (uint32_t)__cvta_generic_to_shared(dst);
    #pragma unroll
    for (int i = 0; i < (WCH / 4) / NTHREADS; ++i) {   // 8
        int j = tid + i * NTHREADS;
        cp16(d0 + j * 16, src + j * 4);
    }
}

// ---------------- precompute kernels ----------------
__global__ void repack_w_kernel(const float* __restrict__ w) {
    int idx = blockIdx.x * blockDim.x + threadIdx.x;
    if (idx >= DTOT * NN) return;
    int j  = idx / WCH;
    int r  = idx % WCH;
    int cl = r / NN;
    int n  = r % NN;
    int kk = j >> 1;
    int c  = (j & 1) * CHALF + cl;
    g_Wr[idx] = w[(c * 25 + kk) * NN + n];
}

__global__ void csum_kernel(const float* __restrict__ x) {
    int idx = blockIdx.x * blockDim.x + threadIdx.x;
    if (idx >= BATCH * H_IN * W_IN) return;
    int b = idx >> 12;
    int p = idx & 4095;
    const float* xp = x + (size_t)b * C_IN * 4096 + p;
    float s = 0.f;
    #pragma unroll
    for (int c = 0; c < C_IN; ++c) s += xp[c * 4096];
    g_csum[idx] = s;
}

__global__ void invs_kernel() {
    int idx = blockIdx.x * blockDim.x + threadIdx.x;
    if (idx >= BATCH * HOUT * WOUT) return;
    int b = idx / (HOUT * WOUT);
    int r = idx % (HOUT * WOUT);
    int y = r / WOUT;
    int xp = r % WOUT;
    float s = 0.f;
    #pragma unroll
    for (int ki = 0; ki < 5; ++ki)
        #pragma unroll
        for (int kj = 0; kj < 5; ++kj)
            s += g_csum[b * 4096 + (y + ki) * 64 + (xp + kj)];
    g_invs[idx] = 1.0f / (s + FEPS);
}

// ---------------- main fused NNMF kernel ----------------
union F4U2 { float4 f4; ull u2[2]; };

extern __shared__ float smem_dyn[];

__global__ void __launch_bounds__(NTHREADS, 3)
nnmf_main(const float* __restrict__ x, float* __restrict__ out) {
    float* xs = smem_dyn;                 // [C_IN][XS_H][XS_W]
    float* ws = smem_dyn + XS_ELEMS;      // [2][CHALF][NN]

    const int b  = blockIdx.z;
    const int y0 = blockIdx.y * TY;
    const int x0 = blockIdx.x * TX;
    const int tid = threadIdx.x;
    const int q   = tid & 3;
    const int gid = tid >> 2;
    const int py  = gid / TXP;
    const int px  = (gid % TXP) * 2;
    const int n0  = q * 24;

    // Load x tile into smem
    {
        const int nf4 = XS_ELEMS / 4;
        for (int i = tid; i < nf4; i += NTHREADS) {
            int c   = i >> 5;
            int rr  = i & 31;
            int dy  = rr >> 2;
            int dxq = rr & 3;
            const float4 v = *(const float4*)(x + (((size_t)(b * C_IN + c) * H_IN + (y0 + dy)) * W_IN + x0) + dxq * 4);
            *(float4*)(xs + c * XS_CH + dy * XS_W + dxq * 4) = v;
        }
    }

    copy_chunk(ws, g_Wr, tid);
    cp_commit();

    const int yy = y0 + py;
    const float inv_a = g_invs[(b * HOUT + yy) * WOUT + (x0 + px)];
    const float inv_b = g_invs[(b * HOUT + yy) * WOUT + (x0 + px + 1)];

    ull ha[12], hb[12], ta[12], tb[12];
    const ull hinit = pack2(1.0f / 96.0f, 1.0f / 96.0f);
    #pragma unroll
    for (int i = 0; i < 12; ++i) { ha[i] = hinit; hb[i] = hinit; }

    for (int it = 0; it < NITERS; ++it) {
        const ull zz = pack2(0.f, 0.f);
        #pragma unroll
        for (int i = 0; i < 12; ++i) { ta[i] = zz; tb[i] = zz; }

        for (int ch = 0; ch < NCHUNK; ++ch) {
            const int cs = it * NCHUNK + ch;
            float* wsbuf = ws + (cs & 1) * WCH;
            if (cs < NITERS * NCHUNK - 1) {
                copy_chunk(ws + ((cs + 1) & 1) * WCH,
                           g_Wr + ((ch + 1) % NCHUNK) * WCH, tid);
                cp_commit();
                cp_wait<1>();
            } else {
                cp_wait<0>();
            }
            __syncthreads();

            const int kk = ch >> 1;
            const int ki = kk / 5, kj = kk % 5;
            const float* xrow = xs + (ch & 1) * CHALF * XS_CH
                                   + (py + ki) * XS_W + (px + kj);
            const float* wbase = wsbuf + n0;

            // register double-buffer for W: pipeline channel c+1's loads
            ull w2a[12], w2b[12];
            #pragma unroll
            for (int i = 0; i < 6; ++i) {
                F4U2 v; v.f4 = *(const float4*)(wbase + i * 4);
                w2a[2 * i]     = v.u2[0];
                w2a[2 * i + 1] = v.u2[1];
            }

            #pragma unroll 2
            for (int cc = 0; cc < CHALF; ++cc) {
                ull* wc = (cc & 1) ? w2b : w2a;
                ull* wn = (cc & 1) ? w2a : w2b;
                if (cc + 1 < CHALF) {
                    const float* wnext = wbase + (cc + 1) * NN;
                    #pragma unroll
                    for (int i = 0; i < 6; ++i) {
                        F4U2 v; v.f4 = *(const float4*)(wnext + i * 4);
                        wn[2 * i]     = v.u2[0];
                        wn[2 * i + 1] = v.u2[1];
                    }
                }
                const float u_a = xrow[cc * XS_CH];
                const float u_b = xrow[cc * XS_CH + 1];

                ull a0 = fmul2(wc[0], ha[0]);
                ull a1 = fmul2(wc[1], ha[1]);
                ull b0 = fmul2(wc[0], hb[0]);
                ull b1 = fmul2(wc[1], hb[1]);
                #pragma unroll
                for (int i = 2; i < 12; i += 2) {
                    a0 = ffma2(wc[i],     ha[i],     a0);
                    a1 = ffma2(wc[i + 1], ha[i + 1], a1);
                    b0 = ffma2(wc[i],     hb[i],     b0);
                    b1 = ffma2(wc[i + 1], hb[i + 1], b1);
                }
                a0 = fadd2(a0, a1);
                b0 = fadd2(b0, b1);
                float alo, ahi, blo, bhi;
                unpack2(a0, alo, ahi);
                unpack2(b0, blo, bhi);
                float da = alo + ahi;
                float db = blo + bhi;
                da += __shfl_xor_sync(0xffffffffu, da, 1);
                db += __shfl_xor_sync(0xffffffffu, db, 1);
                da += __shfl_xor_sync(0xffffffffu, da, 2);
                db += __shfl_xor_sync(0xffffffffu, db, 2);

                const float ra = (u_a * inv_a) * frcp(da + FEPS);
                const float rb = (u_b * inv_b) * frcp(db + FEPS);
                const ull r2a = pack2(ra, ra);
                const ull r2b = pack2(rb, rb);
                #pragma unroll
                for (int i = 0; i < 12; ++i) {
                    ta[i] = ffma2(wc[i], r2a, ta[i]);
                    tb[i] = ffma2(wc[i], r2b, tb[i]);
                }
            }
            __syncthreads();
        }

        #pragma unroll
        for (int i = 0; i < 12; ++i) {
            ha[i] = ffma2(ha[i], ta[i], ha[i]);
            hb[i] = ffma2(hb[i], tb[i], hb[i]);
        }
        ull sa = fadd2(ha[0], ha[1]);
        ull sb = fadd2(hb[0], hb[1]);
        #pragma unroll
        for (int i = 2; i < 12; ++i) { sa = fadd2(sa, ha[i]); sb = fadd2(sb, hb[i]); }
        float slo, shi, tlo, thi;
        unpack2(sa, slo, shi);
        unpack2(sb, tlo, thi);
        float ssa = slo + shi;
        float ssb = tlo + thi;
        ssa += __shfl_xor_sync(0xffffffffu, ssa, 1);
        ssb += __shfl_xor_sync(0xffffffffu, ssb, 1);
        ssa += __shfl_xor_sync(0xffffffffu, ssa, 2);
        ssb += __shfl_xor_sync(0xffffffffu, ssb, 2);
        const float rsa = frcp(ssa + FEPS);
        const float rsb = frcp(ssb + FEPS);
        const ull rsa2 = pack2(rsa, rsa);
        const ull rsb2 = pack2(rsb, rsb);
        #pragma unroll
        for (int i = 0; i < 12; ++i) {
            ha[i] = fmul2(ha[i], rsa2);
            hb[i] = fmul2(hb[i], rsb2);
        }
    }

    const int xx = x0 + px;
    #pragma unroll
    for (int i = 0; i < 12; ++i) {
        float alo, ahi, blo, bhi;
        unpack2(ha[i], alo, ahi);
        unpack2(hb[i], blo, bhi);
        const int n = n0 + 2 * i;
        *(float2*)(out + ((size_t)(b * NN + n)     * HOUT + yy) * WOUT + xx) = make_float2(alo, blo);
        *(float2*)(out + ((size_t)(b * NN + n + 1) * HOUT + yy) * WOUT + xx) = make_float2(ahi, bhi);
    }
}

// ---------------- launch ----------------
extern "C" void kernel_launch(void* const* d_in, const int* in_sizes, int n_in,
                              void* d_out, int out_size) {
    const float* x = (const float*)d_in[0];
    const float* w = (const float*)d_in[1];
    if (n_in >= 2 && in_sizes[0] == DTOT * NN && in_sizes[1] == BATCH * C_IN * H_IN * W_IN) {
        const float* t = x; x = w; w = t;
    }
    float* out = (float*)d_out;

    repack_w_kernel<<<(DTOT * NN + 255) / 256, 256>>>(w);
    csum_kernel<<<(BATCH * H_IN * W_IN + 255) / 256, 256>>>(x);
    invs_kernel<<<(BATCH * HOUT * WOUT + 255) / 256, 256>>>();

    cudaFuncSetAttribute(nnmf_main, cudaFuncAttributeMaxDynamicSharedMemorySize, SMEM_BYTES);
    dim3 grid(WOUT / TX, HOUT / TY, BATCH);   // 1200 blocks
    nnmf_main<<<grid, NTHREADS, SMEM_BYTES>>>(x, out);
}

// round 9
// speedup vs baseline: 9.6881x; 7.4763x over previous
#include <cuda_runtime.h>
#include <cuda_bf16.h>
#include <cstdint>

#define NN      96
#define NPOS    57600
#define NITERS  5
#define FEPS    1e-20f
#define PT      64                 // positions per block
#define NBLK    (NPOS / PT)        // 900
#define NTHR    128                // 4 warps, 1 slab (16 rows) each
#define NCH     25

#define WFRAG_U2 3072              // per-chunk W image: 1536 wj + 1536 wt (uint2)
#define SMEM_BYTES (2 * WFRAG_U2 * 8)   // 49152

__device__ __align__(16) uint2 g_wfrag[NCH * WFRAG_U2];                  // 614 KB
__device__ __align__(16) uint2 g_xn[(size_t)NBLK * NCH * 4 * 8 * 32];    // 184 MB
__device__ float g_csum[16 * 4096];
__device__ float g_invs[NPOS];

// ---------------- helpers ----------------
__device__ __forceinline__ float frcp(float x) {
    float r; asm("rcp.approx.ftz.f32 %0, %1;" : "=f"(r) : "f"(x)); return r;
}
__device__ __forceinline__ uint32_t packbf(float lo, float hi) {
    uint32_t r;
    asm("cvt.rn.bf16x2.f32 %0, %1, %2;" : "=r"(r) : "f"(hi), "f"(lo));
    return r;
}
__device__ __forceinline__ float bflo(uint32_t v) { return __uint_as_float(v << 16); }
__device__ __forceinline__ float bfhi(uint32_t v) { return __uint_as_float(v & 0xFFFF0000u); }

__device__ __forceinline__ void mma_bf16(float c[4], const uint32_t a[4],
                                         uint32_t b0, uint32_t b1) {
    asm("mma.sync.aligned.m16n8k16.row.col.f32.bf16.bf16.f32 "
        "{%0,%1,%2,%3}, {%4,%5,%6,%7}, {%8,%9}, {%0,%1,%2,%3};"
        : "+f"(c[0]), "+f"(c[1]), "+f"(c[2]), "+f"(c[3])
        : "r"(a[0]), "r"(a[1]), "r"(a[2]), "r"(a[3]), "r"(b0), "r"(b1));
}

__device__ __forceinline__ void cp16(uint32_t dst_smem, const void* src) {
    asm volatile("cp.async.cg.shared.global [%0], [%1], 16;" :: "r"(dst_smem), "l"(src));
}
#define CP_COMMIT() asm volatile("cp.async.commit_group;")
template <int N> __device__ __forceinline__ void cp_wait() {
    asm volatile("cp.async.wait_group %0;" :: "n"(N));
}
__device__ __forceinline__ void cp_chunk(uint2* dst, const uint2* src, int tid) {
    uint32_t d0 = (uint32_t)__cvta_generic_to_shared(dst);
    #pragma unroll
    for (int i = 0; i < 12; ++i) {         // 1536 x 16B / 128 threads
        int j = tid + i * NTHR;
        cp16(d0 + j * 16, src + j * 2);
    }
}

// ---------------- precompute ----------------
__global__ void csum_kernel(const float* __restrict__ x) {
    int idx = blockIdx.x * blockDim.x + threadIdx.x;
    if (idx >= 16 * 4096) return;
    int b = idx >> 12, p = idx & 4095;
    const float* xp = x + (size_t)b * 64 * 4096 + p;
    float s = 0.f;
    #pragma unroll
    for (int c = 0; c < 64; ++c) s += xp[c * 4096];
    g_csum[idx] = s;
}
__global__ void invs_kernel() {
    int idx = blockIdx.x * blockDim.x + threadIdx.x;
    if (idx >= NPOS) return;
    int b = idx / 3600, r = idx % 3600, y = r / 60, xp = r % 60;
    float s = 0.f;
    #pragma unroll
    for (int ki = 0; ki < 5; ++ki)
        #pragma unroll
        for (int kj = 0; kj < 5; ++kj) s += g_csum[b * 4096 + (y + ki) * 64 + (xp + kj)];
    g_invs[idx] = 1.0f / (s + FEPS);
}

// W fragment images: wj (B of MMA1) then wt (B of MMA2), both fragment-ordered
__global__ void wfrag_kernel(const float* __restrict__ w) {
    int idx = blockIdx.x * blockDim.x + threadIdx.x;
    if (idx >= NCH * WFRAG_U2) return;
    int kk = idx / WFRAG_U2, r = idx % WFRAG_U2;
    int lane = r & 31, t = r >> 5;
    int gid = lane >> 2, tig = lane & 3;
    uint2 v;
    if (t < 48) {                        // wj: t = s*8 + dt ; B[k=n][col=d]
        int s = t >> 3, dt = t & 7;
        int row = (dt * 8 + gid) * NCH + kk;     // W row for channel d
        int n0 = s * 16 + tig * 2;
        v.x = packbf(w[row * NN + n0],     w[row * NN + n0 + 1]);
        v.y = packbf(w[row * NN + n0 + 8], w[row * NN + n0 + 9]);
    } else {                             // wt: t-48 = s*12 + nt ; B[k=d][col=n]
        int t2 = t - 48;
        int s = t2 / 12, nt = t2 % 12;
        int n = nt * 8 + gid;
        int d0 = s * 16 + tig * 2;
        v.x = packbf(w[(d0 * NCH + kk) * NN + n],       w[((d0 + 1) * NCH + kk) * NN + n]);
        v.y = packbf(w[((d0 + 8) * NCH + kk) * NN + n], w[((d0 + 9) * NCH + kk) * NN + n]);
    }
    g_wfrag[idx] = v;
}

// Xn = X * inv, bf16, stored in m16n8 C-fragment order per (blk, kk, slab, dtile)
__global__ void xn_kernel(const float* __restrict__ x) {
    size_t idx = (size_t)blockIdx.x * blockDim.x + threadIdx.x;
    if (idx >= (size_t)NBLK * NCH * 4 * 8 * 32) return;
    int lane = (int)(idx & 31); size_t r = idx >> 5;
    int dt = (int)(r & 7); r >>= 3;
    int slab = (int)(r & 3); r >>= 2;
    int kk = (int)(r % NCH);
    int blk = (int)(r / NCH);
    int gid = lane >> 2, tig = lane & 3;
    int ki = kk / 5, kj = kk % 5;
    int c0 = dt * 8 + 2 * tig;
    uint32_t res[2];
    #pragma unroll
    for (int e = 0; e < 2; ++e) {
        int p = blk * PT + slab * 16 + gid + e * 8;
        int b = p / 3600, rem = p % 3600, y = rem / 60, xx = rem % 60;
        float inv = g_invs[p];
        size_t base = (((size_t)(b * 64 + c0) * 64) + (y + ki)) * 64 + (xx + kj);
        float f0 = x[base] * inv;
        float f1 = x[base + 64 * 64] * inv;    // channel c0+1
        res[e] = packbf(f0, f1);
    }
    g_xn[idx] = make_uint2(res[0], res[1]);
}

// ---------------- main HMMA kernel ----------------
extern __shared__ __align__(16) uint2 ws[];   // [2][3072]

__global__ void __launch_bounds__(NTHR, 2)
nnmf_hmma(float* __restrict__ out) {
    const int tid  = threadIdx.x;
    const int warp = tid >> 5;
    const int lane = tid & 31;
    const int gid  = lane >> 2;
    const int tig  = lane & 3;

    cp_chunk(ws, g_wfrag, tid);
    CP_COMMIT();

    float hc[12][4];
    #pragma unroll
    for (int t = 0; t < 12; ++t)
        #pragma unroll
        for (int e = 0; e < 4; ++e) hc[t][e] = 1.0f / 96.0f;

    const uint2* xbase = g_xn + ((size_t)blockIdx.x * NCH * 4) * 256 + (size_t)warp * 256 + lane;

    for (int it = 0; it < NITERS; ++it) {
        // H A-fragments (bf16) from f32 C-layout — thread-local
        uint32_t hA[6][4];
        #pragma unroll
        for (int s = 0; s < 6; ++s) {
            hA[s][0] = packbf(hc[2 * s][0],     hc[2 * s][1]);
            hA[s][1] = packbf(hc[2 * s][2],     hc[2 * s][3]);
            hA[s][2] = packbf(hc[2 * s + 1][0], hc[2 * s + 1][1]);
            hA[s][3] = packbf(hc[2 * s + 1][2], hc[2 * s + 1][3]);
        }
        float tc[12][4];
        #pragma unroll
        for (int t = 0; t < 12; ++t)
            #pragma unroll
            for (int e = 0; e < 4; ++e) tc[t][e] = 0.f;

        for (int j = 0; j < NCH; ++j) {
            const int cs = it * NCH + j;
            const uint2* wb = ws + (cs & 1) * WFRAG_U2;
            if (cs < NITERS * NCH - 1) {
                cp_chunk(ws + ((cs + 1) & 1) * WFRAG_U2,
                         g_wfrag + ((j + 1) % NCH) * WFRAG_U2, tid);
                CP_COMMIT();
                cp_wait<1>();
            } else {
                cp_wait<0>();
            }
            __syncthreads();

            // prefetch Xn fragments for this chunk (independent of MMA1)
            uint2 xv[8];
            const uint2* xp = xbase + (size_t)j * 4 * 256;
            #pragma unroll
            for (int dt = 0; dt < 8; ++dt) xv[dt] = __ldg(xp + dt * 32);

            // MMA1: Den[16 x 64] = H[16 x 96] * Wj
            float den[8][4];
            #pragma unroll
            for (int dt = 0; dt < 8; ++dt)
                #pragma unroll
                for (int e = 0; e < 4; ++e) den[dt][e] = 0.f;
            #pragma unroll
            for (int s = 0; s < 6; ++s)
                #pragma unroll
                for (int dt = 0; dt < 8; ++dt) {
                    uint2 b = wb[(s * 8 + dt) * 32 + lane];
                    mma_bf16(den[dt], hA[s], b.x, b.y);
                }

            // ratio (thread-local, C-layout -> A-fragments of MMA2)
            uint32_t rA[4][4];
            #pragma unroll
            for (int dt = 0; dt < 8; ++dt) {
                float r0 = bflo(xv[dt].x) * frcp(den[dt][0] + FEPS);
                float r1 = bfhi(xv[dt].x) * frcp(den[dt][1] + FEPS);
                float r2 = bflo(xv[dt].y) * frcp(den[dt][2] + FEPS);
                float r3 = bfhi(xv[dt].y) * frcp(den[dt][3] + FEPS);
                rA[dt >> 1][(dt & 1) * 2 + 0] = packbf(r0, r1);
                rA[dt >> 1][(dt & 1) * 2 + 1] = packbf(r2, r3);
            }

            // MMA2: T[16 x 96] += R[16 x 64] * Wt
            const uint2* wt = wb + 1536;
            #pragma unroll
            for (int s = 0; s < 4; ++s)
                #pragma unroll
                for (int nt = 0; nt < 12; ++nt) {
                    uint2 b = wt[(s * 12 + nt) * 32 + lane];
                    mma_bf16(tc[nt], rA[s], b.x, b.y);
                }
            __syncthreads();
        }

        // h = h*(1+t); h /= (sum_n h + eps)   (rows gid and gid+8)
        float s0 = 0.f, s1 = 0.f;
        #pragma unroll
        for (int t = 0; t < 12; ++t) {
            hc[t][0] = fmaf(hc[t][0], tc[t][0], hc[t][0]);
            hc[t][1] = fmaf(hc[t][1], tc[t][1], hc[t][1]);
            hc[t][2] = fmaf(hc[t][2], tc[t][2], hc[t][2]);
            hc[t][3] = fmaf(hc[t][3], tc[t][3], hc[t][3]);
            s0 += hc[t][0] + hc[t][1];
            s1 += hc[t][2] + hc[t][3];
        }
        s0 += __shfl_xor_sync(0xffffffffu, s0, 1);
        s1 += __shfl_xor_sync(0xffffffffu, s1, 1);
        s0 += __shfl_xor_sync(0xffffffffu, s0, 2);
        s1 += __shfl_xor_sync(0xffffffffu, s1, 2);
        const float rs0 = frcp(s0 + FEPS);
        const float rs1 = frcp(s1 + FEPS);
        #pragma unroll
        for (int t = 0; t < 12; ++t) {
            hc[t][0] *= rs0; hc[t][1] *= rs0;
            hc[t][2] *= rs1; hc[t][3] *= rs1;
        }
    }

    // output: out[b][n][pos]
    const int p0 = blockIdx.x * PT + warp * 16 + gid;
    #pragma unroll
    for (int e = 0; e < 4; ++e) {
        const int p = p0 + ((e >> 1) ? 8 : 0);
        const int b = p / 3600, pos = p % 3600;
        #pragma unroll
        for (int t = 0; t < 12; ++t) {
            const int n = t * 8 + 2 * tig + (e & 1);
            out[((size_t)(b * NN + n)) * 3600 + pos] = hc[t][e];
        }
    }
}

// ---------------- launch ----------------
extern "C" void kernel_launch(void* const* d_in, const int* in_sizes, int n_in,
                              void* d_out, int out_size) {
    const float* x = (const float*)d_in[0];
    const float* w = (const float*)d_in[1];
    if (n_in >= 2 && in_sizes[0] == 1600 * NN) { const float* t = x; x = w; w = t; }
    float* out = (float*)d_out;

    csum_kernel<<<(16 * 4096 + 255) / 256, 256>>>(x);
    invs_kernel<<<(NPOS + 255) / 256, 256>>>();
    wfrag_kernel<<<(NCH * WFRAG_U2 + 255) / 256, 256>>>(w);
    {
        size_t nxn = (size_t)NBLK * NCH * 4 * 8 * 32;
        xn_kernel<<<(unsigned)((nxn + 255) / 256), 256>>>(x);
    }

    cudaFuncSetAttribute(nnmf_hmma, cudaFuncAttributeMaxDynamicSharedMemorySize, SMEM_BYTES);
    nnmf_hmma<<<NBLK, NTHR, SMEM_BYTES>>>(out);
}

// round 11
// speedup vs baseline: 9.9897x; 1.0311x over previous
#include <cuda_runtime.h>
#include <cuda_bf16.h>
#include <cstdint>

#define NN      96
#define NPOS    57600
#define NITERS  5
#define FEPS    1e-20f
#define PT      64
#define NBLK    (NPOS / PT)        // 900
#define NTHR    128
#define NCH     25

#define WFRAG_U2 1536              // per-chunk W image: wj only (uint2)
#define SMEM_BYTES (2 * WFRAG_U2 * 8)   // 24576

__device__ __align__(16) uint2 g_wfrag[NCH * WFRAG_U2];                  // 307 KB
__device__ __align__(16) uint2 g_xn[(size_t)NBLK * NCH * 4 * 8 * 32];    // 184 MB
__device__ float g_csum[16 * 4096];
__device__ float g_invs[NPOS];

// ---------------- helpers ----------------
__device__ __forceinline__ float frcp(float x) {
    float r; asm("rcp.approx.ftz.f32 %0, %1;" : "=f"(r) : "f"(x)); return r;
}
__device__ __forceinline__ uint32_t packbf(float lo, float hi) {
    uint32_t r;
    asm("cvt.rn.bf16x2.f32 %0, %1, %2;" : "=r"(r) : "f"(hi), "f"(lo));
    return r;
}
__device__ __forceinline__ float bflo(uint32_t v) { return __uint_as_float(v << 16); }
__device__ __forceinline__ float bfhi(uint32_t v) { return __uint_as_float(v & 0xFFFF0000u); }
__device__ __forceinline__ uint32_t movm(uint32_t a) {
    uint32_t d;
    asm("movmatrix.sync.aligned.m8n8.trans.b16 %0, %1;" : "=r"(d) : "r"(a));
    return d;
}

__device__ __forceinline__ void mma_bf16(float c[4], const uint32_t a[4],
                                         uint32_t b0, uint32_t b1) {
    asm("mma.sync.aligned.m16n8k16.row.col.f32.bf16.bf16.f32 "
        "{%0,%1,%2,%3}, {%4,%5,%6,%7}, {%8,%9}, {%0,%1,%2,%3};"
        : "+f"(c[0]), "+f"(c[1]), "+f"(c[2]), "+f"(c[3])
        : "r"(a[0]), "r"(a[1]), "r"(a[2]), "r"(a[3]), "r"(b0), "r"(b1));
}

__device__ __forceinline__ void cp16(uint32_t dst_smem, const void* src) {
    asm volatile("cp.async.cg.shared.global [%0], [%1], 16;" :: "r"(dst_smem), "l"(src));
}
#define CP_COMMIT() asm volatile("cp.async.commit_group;")
template <int N> __device__ __forceinline__ void cp_wait() {
    asm volatile("cp.async.wait_group %0;" :: "n"(N));
}
__device__ __forceinline__ void cp_chunk(uint2* dst, const uint2* src, int tid) {
    uint32_t d0 = (uint32_t)__cvta_generic_to_shared(dst);
    #pragma unroll
    for (int i = 0; i < 6; ++i) {          // 1536 * 8B / 16B / 128 thr
        int j = tid + i * NTHR;
        cp16(d0 + j * 16, src + j * 2);
    }
}

// ---------------- precompute ----------------
__global__ void csum_kernel(const float* __restrict__ x) {
    int idx = blockIdx.x * blockDim.x + threadIdx.x;
    if (idx >= 16 * 4096) return;
    int b = idx >> 12, p = idx & 4095;
    const float* xp = x + (size_t)b * 64 * 4096 + p;
    float s = 0.f;
    #pragma unroll
    for (int c = 0; c < 64; ++c) s += xp[c * 4096];
    g_csum[idx] = s;
}
__global__ void invs_kernel() {
    int idx = blockIdx.x * blockDim.x + threadIdx.x;
    if (idx >= NPOS) return;
    int b = idx / 3600, r = idx % 3600, y = r / 60, xp = r % 60;
    float s = 0.f;
    #pragma unroll
    for (int ki = 0; ki < 5; ++ki)
        #pragma unroll
        for (int kj = 0; kj < 5; ++kj) s += g_csum[b * 4096 + (y + ki) * 64 + (xp + kj)];
    g_invs[idx] = 1.0f / (s + FEPS);
}

// Wj fragment image only: frag (s,dt) at (s*8+dt)*32+lane, B-layout (k=n, col=d)
__global__ void wfrag_kernel(const float* __restrict__ w) {
    int idx = blockIdx.x * blockDim.x + threadIdx.x;
    if (idx >= NCH * WFRAG_U2) return;
    int kk = idx / WFRAG_U2, r = idx % WFRAG_U2;
    int lane = r & 31, t = r >> 5;       // t = s*8 + dt
    int gid = lane >> 2, tig = lane & 3;
    int s = t >> 3, dt = t & 7;
    int row = (dt * 8 + gid) * NCH + kk;     // W row for channel d
    int n0 = s * 16 + tig * 2;
    uint2 v;
    v.x = packbf(w[row * NN + n0],     w[row * NN + n0 + 1]);
    v.y = packbf(w[row * NN + n0 + 8], w[row * NN + n0 + 9]);
    g_wfrag[idx] = v;
}

// Xn = X*inv, bf16, C-fragment order; grid (4, NCH, NBLK), block 256
__global__ void xn_kernel(const float* __restrict__ x) {
    int v = blockIdx.x * 256 + threadIdx.x;          // 0..1023
    int kk = blockIdx.y, blk = blockIdx.z;
    int lane = v & 31, dt = (v >> 5) & 7, slab = v >> 8;
    int gid = lane >> 2, tig = lane & 3;
    int ki = kk / 5, kj = kk % 5;
    int c0 = dt * 8 + 2 * tig;
    uint32_t res[2];
    #pragma unroll
    for (int e = 0; e < 2; ++e) {
        int p = blk * PT + slab * 16 + gid + e * 8;
        int b = p / 3600, rem = p - b * 3600;
        int y = rem / 60, xx = rem - y * 60;
        float inv = g_invs[p];
        size_t base = (((size_t)(b * 64 + c0) * 64) + (y + ki)) * 64 + (xx + kj);
        res[e] = packbf(x[base] * inv, x[base + 4096] * inv);
    }
    g_xn[(((size_t)blk * NCH + kk) * 4 + slab) * 256 + dt * 32 + lane] =
        make_uint2(res[0], res[1]);
}

// ---------------- main HMMA kernel ----------------
extern __shared__ __align__(16) uint2 ws[];   // [2][1536]

__global__ void __launch_bounds__(NTHR, 3)
nnmf_hmma(float* __restrict__ out) {
    const int tid  = threadIdx.x;
    const int warp = tid >> 5;
    const int lane = tid & 31;
    const int gid  = lane >> 2;
    const int tig  = lane & 3;

    cp_chunk(ws, g_wfrag, tid);
    CP_COMMIT();

    float hc[12][4];
    #pragma unroll
    for (int t = 0; t < 12; ++t)
        #pragma unroll
        for (int e = 0; e < 4; ++e) hc[t][e] = 1.0f / 96.0f;

    const uint2* xbase = g_xn + ((size_t)blockIdx.x * NCH * 4) * 256 + (size_t)warp * 256 + lane;

    for (int it = 0; it < NITERS; ++it) {
        uint32_t hA[6][4];
        #pragma unroll
        for (int s = 0; s < 6; ++s) {
            hA[s][0] = packbf(hc[2 * s][0],     hc[2 * s][1]);
            hA[s][1] = packbf(hc[2 * s][2],     hc[2 * s][3]);
            hA[s][2] = packbf(hc[2 * s + 1][0], hc[2 * s + 1][1]);
            hA[s][3] = packbf(hc[2 * s + 1][2], hc[2 * s + 1][3]);
        }
        float tc[12][4];
        #pragma unroll
        for (int t = 0; t < 12; ++t)
            #pragma unroll
            for (int e = 0; e < 4; ++e) tc[t][e] = 0.f;

        for (int j = 0; j < NCH; ++j) {
            const int cs = it * NCH + j;
            const uint2* wb = ws + (cs & 1) * WFRAG_U2;
            if (cs < NITERS * NCH - 1) {
                cp_chunk(ws + ((cs + 1) & 1) * WFRAG_U2,
                         g_wfrag + ((j + 1) % NCH) * WFRAG_U2, tid);
                CP_COMMIT();
                cp_wait<1>();
            } else {
                cp_wait<0>();
            }
            __syncthreads();

            const uint2* xp = xbase + (size_t)j * 4 * 256;

            // MMA1 + ratio, streamed per dt-pair (den regs stay small)
            uint32_t rA[4][4];
            #pragma unroll
            for (int du = 0; du < 4; ++du) {
                uint2 xv0 = __ldg(xp + (2 * du) * 32);
                uint2 xv1 = __ldg(xp + (2 * du + 1) * 32);
                float d0[4] = {0.f, 0.f, 0.f, 0.f};
                float d1[4] = {0.f, 0.f, 0.f, 0.f};
                #pragma unroll
                for (int s = 0; s < 6; ++s) {
                    uint2 b0 = wb[(s * 8 + 2 * du) * 32 + lane];
                    uint2 b1 = wb[(s * 8 + 2 * du + 1) * 32 + lane];
                    mma_bf16(d0, hA[s], b0.x, b0.y);
                    mma_bf16(d1, hA[s], b1.x, b1.y);
                }
                float r00 = bflo(xv0.x) * frcp(d0[0] + FEPS);
                float r01 = bfhi(xv0.x) * frcp(d0[1] + FEPS);
                float r02 = bflo(xv0.y) * frcp(d0[2] + FEPS);
                float r03 = bfhi(xv0.y) * frcp(d0[3] + FEPS);
                float r10 = bflo(xv1.x) * frcp(d1[0] + FEPS);
                float r11 = bfhi(xv1.x) * frcp(d1[1] + FEPS);
                float r12 = bflo(xv1.y) * frcp(d1[2] + FEPS);
                float r13 = bfhi(xv1.y) * frcp(d1[3] + FEPS);
                rA[du][0] = packbf(r00, r01);
                rA[du][1] = packbf(r02, r03);
                rA[du][2] = packbf(r10, r11);
                rA[du][3] = packbf(r12, r13);
            }

            // MMA2: T += R * Wt, with Wt frags derived from Wj via movmatrix
            #pragma unroll
            for (int v = 0; v < 6; ++v) {
                #pragma unroll
                for (int sd = 0; sd < 4; ++sd) {
                    uint2 f0 = wb[(v * 8 + 2 * sd) * 32 + lane];
                    uint2 f1 = wb[(v * 8 + 2 * sd + 1) * 32 + lane];
                    mma_bf16(tc[2 * v],     rA[sd], movm(f0.x), movm(f1.x));
                    mma_bf16(tc[2 * v + 1], rA[sd], movm(f0.y), movm(f1.y));
                }
            }
            __syncthreads();
        }

        // h = h*(1+t); h /= (sum_n h + eps)
        float s0 = 0.f, s1 = 0.f;
        #pragma unroll
        for (int t = 0; t < 12; ++t) {
            hc[t][0] = fmaf(hc[t][0], tc[t][0], hc[t][0]);
            hc[t][1] = fmaf(hc[t][1], tc[t][1], hc[t][1]);
            hc[t][2] = fmaf(hc[t][2], tc[t][2], hc[t][2]);
            hc[t][3] = fmaf(hc[t][3], tc[t][3], hc[t][3]);
            s0 += hc[t][0] + hc[t][1];
            s1 += hc[t][2] + hc[t][3];
        }
        s0 += __shfl_xor_sync(0xffffffffu, s0, 1);
        s1 += __shfl_xor_sync(0xffffffffu, s1, 1);
        s0 += __shfl_xor_sync(0xffffffffu, s0, 2);
        s1 += __shfl_xor_sync(0xffffffffu, s1, 2);
        const float rs0 = frcp(s0 + FEPS);
        const float rs1 = frcp(s1 + FEPS);
        #pragma unroll
        for (int t = 0; t < 12; ++t) {
            hc[t][0] *= rs0; hc[t][1] *= rs0;
            hc[t][2] *= rs1; hc[t][3] *= rs1;
        }
    }

    // output: out[b][n][pos]
    const int p0 = blockIdx.x * PT + warp * 16 + gid;
    #pragma unroll
    for (int e = 0; e < 4; ++e) {
        const int p = p0 + ((e >> 1) ? 8 : 0);
        const int b = p / 3600, pos = p % 3600;
        #pragma unroll
        for (int t = 0; t < 12; ++t) {
            const int n = t * 8 + 2 * tig + (e & 1);
            out[((size_t)(b * NN + n)) * 3600 + pos] = hc[t][e];
        }
    }
}

// ---------------- launch ----------------
extern "C" void kernel_launch(void* const* d_in, const int* in_sizes, int n_in,
                              void* d_out, int out_size) {
    const float* x = (const float*)d_in[0];
    const float* w = (const float*)d_in[1];
    if (n_in >= 2 && in_sizes[0] == 1600 * NN) { const float* t = x; x = w; w = t; }
    float* out = (float*)d_out;

    csum_kernel<<<(16 * 4096 + 255) / 256, 256>>>(x);
    invs_kernel<<<(NPOS + 255) / 256, 256>>>();
    wfrag_kernel<<<(NCH * WFRAG_U2 + 255) / 256, 256>>>(w);
    xn_kernel<<<dim3(4, NCH, NBLK), 256>>>(x);

    cudaFuncSetAttribute(nnmf_hmma, cudaFuncAttributeMaxDynamicSharedMemorySize, SMEM_BYTES);
    nnmf_hmma<<<NBLK, NTHR, SMEM_BYTES>>>(out);
}